// round 16
// baseline (speedup 1.0000x reference)
#include <cuda_runtime.h>
#include <cuda_bf16.h>
#include <math.h>
#include <stdint.h>

#define NN 50000
#define NE 800000
#define FH 192          // HEADS*HID
#define HID 64
#define LOG2E 1.4426950408889634f

// ---------------- scratch (static device globals; no allocation) ----------------
__device__ __align__(16) float g_h[NN * HID];            // 12.8 MB (layer activations)
__device__ __align__(16) __nv_bfloat16 g_zhi[NN * 384];  // aggregated z, bf16 hi (layer0: 3x128)
__device__ __align__(16) __nv_bfloat16 g_zlo[NN * 384];
#define BW_TOT (192*128 + 4*192*64)
__device__ __align__(16) __nv_bfloat16 g_Bhi5[BW_TOT];
__device__ __align__(16) __nv_bfloat16 g_Blo5[BW_TOT];
__device__ __align__(16) float g_Wal6[768 + 4*384];      // [K][6] per layer (el h0..2, er h0..2)
__device__ __align__(16) float4 g_el4[NN];
__device__ __align__(16) float4 g_er4[NN];
__device__ int   g_cnt[NN];
__device__ int   g_rp[NN + 1];
__device__ int   g_wp[NN];
__device__ int   g_col[NE];
__device__ int   g_bsum[64];

__device__ __forceinline__ float lrelu(float x, float s) { return x > 0.f ? x : s * x; }

// ---------------- cp.async helpers ----------------
__device__ __forceinline__ void cpasync16(uint32_t saddr, const void* gaddr, uint32_t srcbytes) {
    asm volatile("cp.async.ca.shared.global [%0], [%1], 16, %2;"
                 :: "r"(saddr), "l"(gaddr), "r"(srcbytes));
}
__device__ __forceinline__ void cp_commit() {
    asm volatile("cp.async.commit_group;");
}
template <int N>
__device__ __forceinline__ void cp_wait() {
    asm volatile("cp.async.wait_group %0;" :: "n"(N));
}

// ---------------- CSR build (forked stream) ----------------
__global__ void k_zero() {
    int i = blockIdx.x * blockDim.x + threadIdx.x;
    if (i < NN) g_cnt[i] = 0;
}
__global__ void k_hist(const int* __restrict__ dst) {
    int e = blockIdx.x * blockDim.x + threadIdx.x;
    if (e < NE) atomicAdd(&g_cnt[dst[e]], 1);
}
__global__ __launch_bounds__(1024) void k_scanA() {
    __shared__ int wsum[32];
    int tid = threadIdx.x, lane = tid & 31, wid = tid >> 5;
    int i = blockIdx.x * 1024 + tid;
    int v = (i < NN) ? g_cnt[i] : 0;
    int x = v;
    #pragma unroll
    for (int o = 1; o < 32; o <<= 1) {
        int t = __shfl_up_sync(0xffffffffu, x, o);
        if (lane >= o) x += t;
    }
    if (lane == 31) wsum[wid] = x;
    __syncthreads();
    if (wid == 0) {
        int y = wsum[lane];
        #pragma unroll
        for (int o = 1; o < 32; o <<= 1) {
            int t = __shfl_up_sync(0xffffffffu, y, o);
            if (lane >= o) y += t;
        }
        wsum[lane] = y;
    }
    __syncthreads();
    int pre = (wid ? wsum[wid - 1] : 0) + x - v;
    if (i < NN) g_rp[i] = pre;
    if (tid == 1023) g_bsum[blockIdx.x] = pre + v;
}
__global__ __launch_bounds__(1024) void k_scanB(int nblk) {
    __shared__ int sb[64];
    int tid = threadIdx.x;
    if (tid < nblk) sb[tid] = g_bsum[tid];
    __syncthreads();
    int off = 0;
    for (int j = 0; j < (int)blockIdx.x; j++) off += sb[j];
    int i = blockIdx.x * 1024 + tid;
    if (i < NN) {
        int v = g_rp[i] + off;
        g_rp[i] = v;
        g_wp[i] = v;
    }
    if (blockIdx.x == gridDim.x - 1 && tid == 0) {
        int tot = 0;
        for (int j = 0; j < nblk; j++) tot += sb[j];
        g_rp[NN] = tot;
    }
}
__global__ void k_scatter(const int* __restrict__ src, const int* __restrict__ dst) {
    int e = blockIdx.x * blockDim.x + threadIdx.x;
    if (e < NE) {
        int p = atomicAdd(&g_wp[dst[e]], 1);
        g_col[p] = src[e];
    }
}

// ---------------- prep: W splits + Wal6 = LOG2E * W @ al/ar ----------------
__global__ void k_prep(const float* __restrict__ W0, const float* __restrict__ W1,
                       const float* __restrict__ W2, const float* __restrict__ W3,
                       const float* __restrict__ W4,
                       const float* __restrict__ al0, const float* __restrict__ al1,
                       const float* __restrict__ al2, const float* __restrict__ al3,
                       const float* __restrict__ al4,
                       const float* __restrict__ ar0, const float* __restrict__ ar1,
                       const float* __restrict__ ar2, const float* __restrict__ ar3,
                       const float* __restrict__ ar4) {
    int i = blockIdx.x * blockDim.x + threadIdx.x;
    if (i < BW_TOT) {
        int l, j, K, off;
        if (i < 192 * 128) { l = 0; j = i; K = 128; off = 0; }
        else {
            int r = i - 192 * 128;
            l = 1 + r / (192 * 64);
            j = r % (192 * 64);
            K = 64;
            off = 192 * 128 + (l - 1) * 192 * 64;
        }
        const float* W = (l == 0) ? W0 : (l == 1) ? W1 : (l == 2) ? W2 : (l == 3) ? W3 : W4;
        int k = j / FH, n = j % FH;
        float v = W[j];
        __nv_bfloat16 h = __float2bfloat16(v);
        g_Bhi5[off + n * K + k] = h;
        g_Blo5[off + n * K + k] = __float2bfloat16(v - __bfloat162float(h));
    }
    if (i < 2304) {
        int l, k, j, off;
        if (i < 768) { l = 0; k = i / 6; j = i % 6; off = 0; }
        else {
            int r = i - 768;
            l = 1 + r / 384;
            int q = r % 384;
            k = q / 6; j = q % 6;
            off = 768 + (l - 1) * 384;
        }
        const float* W = (l == 0) ? W0 : (l == 1) ? W1 : (l == 2) ? W2 : (l == 3) ? W3 : W4;
        int h = j % 3;
        const float* v;
        if (j < 3) v = (l == 0) ? al0 : (l == 1) ? al1 : (l == 2) ? al2 : (l == 3) ? al3 : al4;
        else       v = (l == 0) ? ar0 : (l == 1) ? ar1 : (l == 2) ? ar2 : (l == 3) ? ar3 : ar4;
        float s = 0.f;
        #pragma unroll 8
        for (int f = 0; f < 64; f++)
            s += W[k * FH + h * 64 + f] * v[h * 64 + f];
        g_Wal6[off + k * 6 + j] = s * LOG2E;
    }
}

// ---------------- layer-0 logits: el/er = x @ Wal6(0) ----------------
__global__ void k_logits0(const float* __restrict__ x) {
    int w = (blockIdx.x * blockDim.x + threadIdx.x) >> 5;
    int lane = threadIdx.x & 31;
    if (w >= NN) return;
    float4 v = ((const float4*)(x + (size_t)w * 128))[lane];
    float p[6] = {0.f, 0.f, 0.f, 0.f, 0.f, 0.f};
    #pragma unroll
    for (int i = 0; i < 4; i++) {
        int k = 4 * lane + i;
        float vi = (i == 0) ? v.x : (i == 1) ? v.y : (i == 2) ? v.z : v.w;
        #pragma unroll
        for (int j = 0; j < 6; j++) p[j] += vi * g_Wal6[k * 6 + j];
    }
    #pragma unroll
    for (int j = 0; j < 6; j++)
        #pragma unroll
        for (int o = 16; o; o >>= 1) p[j] += __shfl_xor_sync(0xffffffffu, p[j], o);
    if (lane == 0) {
        g_el4[w] = make_float4(p[0], p[1], p[2], 0.f);
        g_er4[w] = make_float4(p[3], p[4], p[5], 0.f);
    }
}

// ---------------- aggregation: online softmax, gather h_in (shared across heads),
// write per-head weighted sums z as bf16 hi/lo ----------------
template <int KD>
__global__ __launch_bounds__(256) void k_agg(const float* __restrict__ srcbuf) {
    int w = (blockIdx.x * blockDim.x + threadIdx.x) >> 5;
    int lane = threadIdx.x & 31;
    if (w >= NN) return;
    int beg = g_rp[w], end = g_rp[w + 1];
    float4 er = g_er4[w];

    float m0 = -1e30f, m1 = -1e30f, m2 = -1e30f;
    float s0 = 0.f, s1 = 0.f, s2 = 0.f;
    float a0[4] = {0.f,0.f,0.f,0.f}, a1[4] = {0.f,0.f,0.f,0.f}, a2[4] = {0.f,0.f,0.f,0.f};
    const int NL = (KD == 128) ? 4 : 2;

    for (int e = beg; e < end; e++) {
        int s = g_col[e];
        float4 el = g_el4[s];
        float x0 = lrelu(el.x + er.x, 0.2f);
        float x1 = lrelu(el.y + er.y, 0.2f);
        float x2 = lrelu(el.z + er.z, 0.2f);
        if (x0 > m0) { float sc = exp2f(m0 - x0); s0 *= sc;
            #pragma unroll
            for (int i = 0; i < NL; i++) a0[i] *= sc; m0 = x0; }
        if (x1 > m1) { float sc = exp2f(m1 - x1); s1 *= sc;
            #pragma unroll
            for (int i = 0; i < NL; i++) a1[i] *= sc; m1 = x1; }
        if (x2 > m2) { float sc = exp2f(m2 - x2); s2 *= sc;
            #pragma unroll
            for (int i = 0; i < NL; i++) a2[i] *= sc; m2 = x2; }
        float w0 = exp2f(x0 - m0), w1 = exp2f(x1 - m1), w2 = exp2f(x2 - m2);
        s0 += w0; s1 += w1; s2 += w2;
        float v[4];
        if (KD == 128) {
            float4 vv = ((const float4*)(srcbuf + (size_t)s * 128))[lane];
            v[0] = vv.x; v[1] = vv.y; v[2] = vv.z; v[3] = vv.w;
        } else {
            float2 vv = ((const float2*)(srcbuf + (size_t)s * 64))[lane];
            v[0] = vv.x; v[1] = vv.y; v[2] = 0.f; v[3] = 0.f;
        }
        #pragma unroll
        for (int i = 0; i < NL; i++) {
            a0[i] += w0 * v[i];
            a1[i] += w1 * v[i];
            a2[i] += w2 * v[i];
        }
    }
    float i0 = s0 > 0.f ? 1.f / s0 : 0.f;
    float i1 = s1 > 0.f ? 1.f / s1 : 0.f;
    float i2 = s2 > 0.f ? 1.f / s2 : 0.f;
    const int ZSTR = 3 * KD;
    float* acc[3] = {a0, a1, a2};
    float inv[3] = {i0, i1, i2};
    #pragma unroll
    for (int h = 0; h < 3; h++) {
        #pragma unroll
        for (int q = 0; q < NL / 2; q++) {
            float zx = acc[h][2 * q]     * inv[h];
            float zy = acc[h][2 * q + 1] * inv[h];
            __nv_bfloat16 hx = __float2bfloat16(zx);
            __nv_bfloat16 hy = __float2bfloat16(zy);
            __nv_bfloat16 lx = __float2bfloat16(zx - __bfloat162float(hx));
            __nv_bfloat16 ly = __float2bfloat16(zy - __bfloat162float(hy));
            size_t off = (size_t)w * ZSTR + h * KD;
            ((__nv_bfloat162*)(g_zhi + off))[(NL / 2) * lane + q] = __nv_bfloat162(hx, hy);
            ((__nv_bfloat162*)(g_zlo + off))[(NL / 2) * lane + q] = __nv_bfloat162(lx, ly);
        }
    }
}

// ---------------- block-diag GEMM: out_h = z_h @ W_h; epilogue: +b, lrelu, head-mean
// -> g_h; fused next-layer logits via Wal6 ----------------
__device__ __forceinline__ void mma16816(float* d, const uint32_t* a, const uint32_t* b) {
    asm volatile("mma.sync.aligned.m16n8k16.row.col.f32.bf16.bf16.f32 "
        "{%0,%1,%2,%3}, {%4,%5,%6,%7}, {%8,%9}, {%0,%1,%2,%3};"
        : "+f"(d[0]), "+f"(d[1]), "+f"(d[2]), "+f"(d[3])
        : "r"(a[0]), "r"(a[1]), "r"(a[2]), "r"(a[3]), "r"(b[0]), "r"(b[1]));
}
#define ASTR 24
// smem (elems): A: 2buf x 2half x 3head x 3072 = 36864 ; B: 2buf x 2half x 4608 = 18432
#define SM_B_OFF 36864
#define SM_L_OFF ((36864 + 18432) * 2)          // bytes
#define SM_TOTAL (SM_L_OFF + 4 * 128 * 6 * 4)   // 122880 B

template <int K>
__global__ __launch_bounds__(512, 1) void k_gemm_mma(int boff, const float* __restrict__ b,
                                                     const float* __restrict__ wal6n) {
    extern __shared__ __nv_bfloat16 smem[];
    __nv_bfloat16* sA = smem;
    __nv_bfloat16* sB = smem + SM_B_OFF;
    float* s_l = (float*)((char*)smem + SM_L_OFF);
    const int NT = K / 16;
    const int ZSTR = 3 * K;

    int tid = threadIdx.x, lane = tid & 31, w = tid >> 5;
    int mw = w & 3, nw = w >> 2;
    int m0 = blockIdx.x * 128;
    int g = lane >> 2, t = lane & 3;

    uint32_t sAb = (uint32_t)__cvta_generic_to_shared(sA);
    uint32_t sBb = (uint32_t)__cvta_generic_to_shared(sB);
    const __nv_bfloat16* gAp[3];
    uint32_t dstA[3], okA[3];
    #pragma unroll
    for (int it = 0; it < 3; it++) {
        int idx = tid + it * 512;
        int half = idx / 768, rem = idx % 768;
        int head = rem >> 8, j = rem & 255, r = j >> 1, p = j & 1;
        gAp[it] = (half ? g_zlo : g_zhi) + (size_t)(m0 + r) * ZSTR + head * K + p * 8;
        okA[it] = (m0 + r < NN) ? 16u : 0u;
        dstA[it] = sAb + (uint32_t)(half * 9216 + head * 3072 + r * ASTR + p * 8) * 2;
    }
    int half0 = tid / 384, j0 = tid % 384, r0 = j0 >> 1, p0 = j0 & 1;
    const __nv_bfloat16* gB0 = (half0 ? g_Blo5 : g_Bhi5) + boff + r0 * K + p0 * 8;
    uint32_t dstB0 = sBb + (uint32_t)(half0 * 4608 + r0 * ASTR + p0 * 8) * 2;
    int j1 = tid + 128, r1 = j1 >> 1, p1 = j1 & 1;
    const __nv_bfloat16* gB1 = g_Blo5 + boff + r1 * K + p1 * 8;
    uint32_t dstB1 = sBb + (uint32_t)(4608 + r1 * ASTR + p1 * 8) * 2;

    float d[2][6][4];
    #pragma unroll
    for (int i = 0; i < 2; i++)
        #pragma unroll
        for (int j = 0; j < 6; j++)
            #pragma unroll
            for (int q = 0; q < 4; q++) d[i][j][q] = 0.f;

    #pragma unroll
    for (int it = 0; it < 3; it++) cpasync16(dstA[it], gAp[it], okA[it]);
    cpasync16(dstB0, gB0, 16u);
    if (tid < 256) cpasync16(dstB1, gB1, 16u);
    cp_commit();

    #pragma unroll
    for (int kt = 0; kt < NT; kt++) {
        int buf = kt & 1;
        if (kt + 1 < NT) {
            int nbuf = (kt + 1) & 1;
            int k0 = (kt + 1) * 16;
            #pragma unroll
            for (int it = 0; it < 3; it++)
                cpasync16(dstA[it] + nbuf * 36864, gAp[it] + k0, okA[it]);
            cpasync16(dstB0 + nbuf * 18432, gB0 + k0, 16u);
            if (tid < 256) cpasync16(dstB1 + nbuf * 18432, gB1 + k0, 16u);
            cp_commit();
            cp_wait<1>();
        } else {
            cp_wait<0>();
        }
        __syncthreads();

        const __nv_bfloat16* Abuf = sA + buf * 18432;
        const __nv_bfloat16* Bbuf = sB + buf * 9216;
        #pragma unroll
        for (int h = 0; h < 3; h++) {
            uint32_t afr[2][2][4];
            #pragma unroll
            for (int half = 0; half < 2; half++)
                #pragma unroll
                for (int mt = 0; mt < 2; mt++) {
                    const __nv_bfloat16* base = Abuf + half * 9216 + h * 3072
                                              + (mw * 32 + mt * 16) * ASTR;
                    afr[half][mt][0] = *(const uint32_t*)(base + g * ASTR + 2 * t);
                    afr[half][mt][1] = *(const uint32_t*)(base + (g + 8) * ASTR + 2 * t);
                    afr[half][mt][2] = *(const uint32_t*)(base + g * ASTR + 2 * t + 8);
                    afr[half][mt][3] = *(const uint32_t*)(base + (g + 8) * ASTR + 2 * t + 8);
                }
            uint32_t bfr[2][2][2];
            #pragma unroll
            for (int half = 0; half < 2; half++)
                #pragma unroll
                for (int p = 0; p < 2; p++) {
                    const __nv_bfloat16* base = Bbuf + half * 4608
                                              + (h * 64 + nw * 16 + p * 8) * ASTR;
                    bfr[half][p][0] = *(const uint32_t*)(base + g * ASTR + 2 * t);
                    bfr[half][p][1] = *(const uint32_t*)(base + g * ASTR + 2 * t + 8);
                }
            #pragma unroll
            for (int mt = 0; mt < 2; mt++)
                #pragma unroll
                for (int p = 0; p < 2; p++) {
                    mma16816(d[mt][h * 2 + p], afr[0][mt], bfr[0][p]);
                    mma16816(d[mt][h * 2 + p], afr[0][mt], bfr[1][p]);
                    mma16816(d[mt][h * 2 + p], afr[1][mt], bfr[0][p]);
                }
        }
        __syncthreads();
    }

    // epilogue: bias + lrelu + head-mean -> g_h ; fused next-layer logits
    #pragma unroll
    for (int mt = 0; mt < 2; mt++) {
        #pragma unroll
        for (int gg = 0; gg < 2; gg++) {
            int row = m0 + mw * 32 + mt * 16 + g + gg * 8;
            float q6[6] = {0.f,0.f,0.f,0.f,0.f,0.f};
            #pragma unroll
            for (int p = 0; p < 2; p++) {
                int c0 = nw * 16 + p * 8 + 2 * t;
                float hv[2];
                #pragma unroll
                for (int i = 0; i < 2; i++) {
                    int c = c0 + i;
                    float f0 = lrelu(d[mt][0 + p][gg * 2 + i] + b[c],        0.01f);
                    float f1 = lrelu(d[mt][2 + p][gg * 2 + i] + b[64 + c],   0.01f);
                    float f2 = lrelu(d[mt][4 + p][gg * 2 + i] + b[128 + c],  0.01f);
                    hv[i] = (f0 + f1 + f2) * (1.f / 3.f);
                }
                if (row < NN)
                    *(float2*)&g_h[(size_t)row * HID + c0] = make_float2(hv[0], hv[1]);
                if (wal6n) {
                    #pragma unroll
                    for (int j = 0; j < 6; j++)
                        q6[j] += hv[0] * wal6n[c0 * 6 + j] + hv[1] * wal6n[(c0 + 1) * 6 + j];
                }
            }
            if (wal6n) {
                #pragma unroll
                for (int j = 0; j < 6; j++) {
                    q6[j] += __shfl_xor_sync(0xffffffffu, q6[j], 1);
                    q6[j] += __shfl_xor_sync(0xffffffffu, q6[j], 2);
                }
                if (t == 0) {
                    int rl = mw * 32 + mt * 16 + g + gg * 8;
                    #pragma unroll
                    for (int j = 0; j < 6; j++)
                        s_l[(nw * 128 + rl) * 6 + j] = q6[j];
                }
            }
        }
    }
    if (wal6n) {
        __syncthreads();
        for (int idx = tid; idx < 768; idx += 512) {
            int row = idx / 6, j = idx % 6;
            float s = s_l[row * 6 + j] + s_l[(128 + row) * 6 + j]
                    + s_l[(256 + row) * 6 + j] + s_l[(384 + row) * 6 + j];
            int r = m0 + row;
            if (r < NN) {
                if (j < 3) ((float*)&g_el4[r])[j] = s;
                else       ((float*)&g_er4[r])[j - 3] = s;
            }
        }
    }
}

// ---------------- classifier ----------------
__global__ void k_out(const float* __restrict__ Wo, const float* __restrict__ bo,
                      float* __restrict__ out) {
    int w = (blockIdx.x * blockDim.x + threadIdx.x) >> 5;
    int lane = threadIdx.x & 31;
    if (w >= NN) return;
    float h0 = g_h[(size_t)w * HID + lane];
    float h1 = g_h[(size_t)w * HID + lane + 32];
    #pragma unroll
    for (int c = 0; c < 8; c++) {
        float v = h0 * Wo[lane * 8 + c] + h1 * Wo[(lane + 32) * 8 + c];
        #pragma unroll
        for (int o = 16; o; o >>= 1) v += __shfl_xor_sync(0xffffffffu, v, o);
        if (lane == 0) out[w * 8 + c] = v + bo[c];
    }
}

// ---------------- launch ----------------
extern "C" void kernel_launch(void* const* d_in, const int* in_sizes, int n_in,
                              void* d_out, int out_size) {
    const float* x   = (const float*)d_in[0];
    const int*   src = (const int*)d_in[1];
    const int*   dst = (const int*)d_in[2];
    const float *W[5], *b[5], *al[5], *ar[5];
    for (int l = 0; l < 5; l++) {
        W[l]  = (const float*)d_in[3 + 4 * l];
        b[l]  = (const float*)d_in[4 + 4 * l];
        al[l] = (const float*)d_in[5 + 4 * l];
        ar[l] = (const float*)d_in[6 + 4 * l];
    }
    const float* Wo = (const float*)d_in[23];
    const float* bo = (const float*)d_in[24];
    float* out = (float*)d_out;

    cudaFuncSetAttribute(k_gemm_mma<128>, cudaFuncAttributeMaxDynamicSharedMemorySize, SM_TOTAL);
    cudaFuncSetAttribute(k_gemm_mma<64>,  cudaFuncAttributeMaxDynamicSharedMemorySize, SM_TOTAL);

    // device addresses of __device__ symbols (MUST go through cudaGetSymbolAddress)
    float* wal6_dev = nullptr;
    float* gh_dev = nullptr;
    cudaGetSymbolAddress((void**)&wal6_dev, g_Wal6);
    cudaGetSymbolAddress((void**)&gh_dev, g_h);
    auto wal6 = [&](int l) -> const float* {
        return wal6_dev + (l == 0 ? 0 : 768 + (l - 1) * 384);
    };

    // forked capture stream for the CSR chain
    cudaStream_t s2;
    cudaEvent_t evFork, evJoin;
    cudaStreamCreateWithFlags(&s2, cudaStreamNonBlocking);
    cudaEventCreateWithFlags(&evFork, cudaEventDisableTiming);
    cudaEventCreateWithFlags(&evJoin, cudaEventDisableTiming);

    int nblk = (NN + 1023) / 1024;
    cudaEventRecord(evFork, 0);
    cudaStreamWaitEvent(s2, evFork, 0);
    k_zero<<<(NN + 255) / 256, 256, 0, s2>>>();
    k_hist<<<(NE + 255) / 256, 256, 0, s2>>>(dst);
    k_scanA<<<nblk, 1024, 0, s2>>>();
    k_scanB<<<nblk, 1024, 0, s2>>>(nblk);
    k_scatter<<<(NE + 255) / 256, 256, 0, s2>>>(src, dst);
    cudaEventRecord(evJoin, s2);

    // main stream
    k_prep<<<(BW_TOT + 255) / 256, 256>>>(W[0], W[1], W[2], W[3], W[4],
                                          al[0], al[1], al[2], al[3], al[4],
                                          ar[0], ar[1], ar[2], ar[3], ar[4]);
    int wgrid = (NN * 32 + 255) / 256;
    int ggrid = (NN + 127) / 128;
    k_logits0<<<wgrid, 256>>>(x);
    cudaStreamWaitEvent(0, evJoin, 0);

    for (int l = 0; l < 5; l++) {
        int boff = (l == 0) ? 0 : 192 * 128 + (l - 1) * 192 * 64;
        const float* wn = (l == 4) ? nullptr : wal6(l + 1);
        if (l == 0) {
            k_agg<128><<<wgrid, 256>>>(x);
            k_gemm_mma<128><<<ggrid, 512, SM_TOTAL>>>(boff, b[l], wn);
        } else {
            k_agg<64><<<wgrid, 256>>>(gh_dev);
            k_gemm_mma<64><<<ggrid, 512, SM_TOTAL>>>(boff, b[l], wn);
        }
    }
    k_out<<<wgrid, 256>>>(Wo, bo, out);
}